// round 16
// baseline (speedup 1.0000x reference)
#include <cuda_runtime.h>
#include <cuda_fp16.h>
#include <cstdint>

#define M_TOT 8192
#define N_TOT 11008
#define K_TOT 4096
#define BM 256
#define BN 128
#define BK 64
#define NSTG 4
#define NK (K_TOT / BK)                 // 64
#define IMG_B 16384                     // one 128x64 fp16 tile image (128 rows x 128B)
#define STAGE_B (3 * IMG_B)             // 49152: A(2 images) + B(1 image)
#define SM_STAGE0 1024                  // stages start after barrier block
#define SMEM_TOTAL (SM_STAGE0 + NSTG * STAGE_B)   // 197632
#define NSM 148
#define NTILE ((M_TOT / BM) * (N_TOT / BN))  // 2752
#define MT128 (M_TOT / 128)             // 64
#define NT128 (N_TOT / 128)             // 86

// swizzled tile-image scratch (no cudaMalloc allowed)
__device__ __align__(16384) unsigned char g_xt[(size_t)MT128 * NK * IMG_B]; // 64 MB
__device__ __align__(16384) unsigned char g_wt[(size_t)NT128 * NK * IMG_B]; // 88 MB

__device__ __forceinline__ uint32_t sw128(uint32_t o) { return o ^ ((o >> 3) & 0x70u); }

// ---------------- prepass: x fp32 -> fp16 swizzled tile images ----------------
__global__ void convert_x_kernel(const float* __restrict__ x) {
    int idx = blockIdx.x * blockDim.x + threadIdx.x;   // one 8-vector
    int m  = idx >> 9;
    int kk = (idx & 511) << 3;
    const float4* src = reinterpret_cast<const float4*>(x + (size_t)m * K_TOT + kk);
    float4 a = src[0], b = src[1];
    __half2 h0 = __floats2half2_rn(a.x, a.y), h1 = __floats2half2_rn(a.z, a.w);
    __half2 h2 = __floats2half2_rn(b.x, b.y), h3 = __floats2half2_rn(b.z, b.w);
    uint4 v;
    v.x = *reinterpret_cast<uint32_t*>(&h0); v.y = *reinterpret_cast<uint32_t*>(&h1);
    v.z = *reinterpret_cast<uint32_t*>(&h2); v.w = *reinterpret_cast<uint32_t*>(&h3);
    int mt = m >> 7, r = m & 127, kt = kk >> 6, c = kk & 63;
    size_t off = ((size_t)(mt * NK + kt) << 14) + sw128((uint32_t)(r * 128 + c * 2));
    *reinterpret_cast<uint4*>(g_xt + off) = v;
}

// ---------------- prepass: W int32 -> fp16 (w*s+z) swizzled tile images ----------------
__global__ void dequant_kernel(const int* __restrict__ w, const float* __restrict__ sz) {
    int idx = blockIdx.x * blockDim.x + threadIdx.x;
    int n  = idx >> 9;
    int kk = (idx & 511) << 3;
    int g  = kk >> 7;                  // group of 128
    size_t si = ((size_t)g * N_TOT + n) * 2;
    float s = sz[si], z = sz[si + 1];
    const int4* wp = reinterpret_cast<const int4*>(w + (size_t)n * K_TOT + kk);
    int4 w0 = wp[0], w1 = wp[1];
    __half2 h0 = __floats2half2_rn(fmaf((float)w0.x, s, z), fmaf((float)w0.y, s, z));
    __half2 h1 = __floats2half2_rn(fmaf((float)w0.z, s, z), fmaf((float)w0.w, s, z));
    __half2 h2 = __floats2half2_rn(fmaf((float)w1.x, s, z), fmaf((float)w1.y, s, z));
    __half2 h3 = __floats2half2_rn(fmaf((float)w1.z, s, z), fmaf((float)w1.w, s, z));
    uint4 v;
    v.x = *reinterpret_cast<uint32_t*>(&h0); v.y = *reinterpret_cast<uint32_t*>(&h1);
    v.z = *reinterpret_cast<uint32_t*>(&h2); v.w = *reinterpret_cast<uint32_t*>(&h3);
    int nt = n >> 7, r = n & 127, kt = kk >> 6, c = kk & 63;
    size_t off = ((size_t)(nt * NK + kt) << 14) + sw128((uint32_t)(r * 128 + c * 2));
    *reinterpret_cast<uint4*>(g_wt + off) = v;
}

// ---------------- helpers ----------------
__device__ __forceinline__ uint32_t smem_u32(const void* p) {
    uint32_t a;
    asm("{ .reg .u64 t; cvta.to.shared.u64 t, %1; cvt.u32.u64 %0, t; }" : "=r"(a) : "l"(p));
    return a;
}
#define MBARRIER_INIT(addr, cnt) \
    asm volatile("mbarrier.init.shared.b64 [%0], %1;" :: "r"((uint32_t)(addr)), "r"((uint32_t)(cnt)) : "memory")
#define MBARRIER_EXPECT_TX(addr, b) \
    asm volatile("mbarrier.arrive.expect_tx.shared.b64 _, [%0], %1;" :: "r"((uint32_t)(addr)), "r"((uint32_t)(b)) : "memory")
#define MBARRIER_ARRIVE(addr) \
    asm volatile("mbarrier.arrive.shared.b64 _, [%0];" :: "r"((uint32_t)(addr)) : "memory")
#define MBARRIER_WAIT_PARITY(mbar, par) do { \
    uint32_t _m = (mbar), _p = (par), _d; \
    asm volatile("{ .reg .pred p; mbarrier.try_wait.parity.acquire.cta.shared::cta.b64 p, [%1], %2; " \
                 "selp.b32 %0, 1, 0, p; }" : "=r"(_d) : "r"(_m), "r"(_p) : "memory"); \
    if (!_d) { \
        asm volatile("{ .reg .pred P1; WL%=: mbarrier.try_wait.parity.acquire.cta.shared::cta.b64 P1, [%0], %1, 0x989680; " \
                     "@P1 bra.uni WD%=; bra.uni WL%=; WD%=: }" :: "r"(_m), "r"(_p) : "memory"); \
    } \
} while (0)

__device__ __forceinline__ void bulk_g2s(uint32_t dst, const void* src, uint32_t bytes, uint32_t mbar) {
    asm volatile("cp.async.bulk.shared::cluster.global.mbarrier::complete_tx::bytes [%0], [%1], %2, [%3];"
                 :: "r"(dst), "l"(src), "r"(bytes), "r"(mbar) : "memory");
}
__device__ __forceinline__ void ldsm_x4(uint32_t& r0, uint32_t& r1, uint32_t& r2, uint32_t& r3,
                                        uint32_t addr) {
    asm volatile("ldmatrix.sync.aligned.m8n8.x4.shared.b16 {%0,%1,%2,%3}, [%4];"
                 : "=r"(r0), "=r"(r1), "=r"(r2), "=r"(r3) : "r"(addr));
}
__device__ __forceinline__ void mma16816(float* c, const uint32_t* a, uint32_t b0, uint32_t b1) {
    asm volatile("mma.sync.aligned.m16n8k16.row.col.f32.f16.f16.f32 "
                 "{%0,%1,%2,%3}, {%4,%5,%6,%7}, {%8,%9}, {%0,%1,%2,%3};"
                 : "+f"(c[0]), "+f"(c[1]), "+f"(c[2]), "+f"(c[3])
                 : "r"(a[0]), "r"(a[1]), "r"(a[2]), "r"(a[3]), "r"(b0), "r"(b1));
}
__device__ __forceinline__ void st_cs_v2(float* p, float a, float b) {
    asm volatile("st.global.cs.v2.f32 [%0], {%1,%2};" :: "l"(p), "f"(a), "f"(b) : "memory");
}

// ------- GEMM: persistent, 256x128 tile, warp-specialized mbarrier pipeline -------
// 17 warps: 0-15 compute (64x32 each), 16 producer (cp.async.bulk of tile images).
// full[s]: count 1 (producer expect_tx arrive) + 49152 tx bytes.
// empty[s]: count 16 (one arrive per compute warp).
__global__ __launch_bounds__(544, 1)
void gemm_kernel(const float* __restrict__ bias, float* __restrict__ out) {
    extern __shared__ __align__(1024) char smem[];
    uint32_t sb = smem_u32(smem);
    int tid = threadIdx.x, wid = tid >> 5, lane = tid & 31;
    int bid = blockIdx.x;
    int ntiles_mine = (NTILE - bid + NSM - 1) / NSM;   // tiles bid, bid+148, ...
    int total = ntiles_mine * NK;

    if (tid == 0) {
        for (int s = 0; s < NSTG; s++) {
            MBARRIER_INIT(sb + s * 16, 1);        // full[s]
            MBARRIER_INIT(sb + s * 16 + 8, 16);   // empty[s]
        }
    }
    __syncthreads();

    if (wid == 16) {
        // ---------------- producer warp ----------------
        for (int g = 0; g < total; g++) {
            int slot = g & 3;
            if (g >= NSTG)
                MBARRIER_WAIT_PARITY(sb + slot * 16 + 8, ((g >> 2) - 1) & 1);
            if (lane == 0) {
                int t = g >> 6, kt = g & 63;
                int cl = bid + t * NSM;
                int tm = cl & 31, tn = cl >> 5;    // M-fastest: A stays L2-resident
                const unsigned char* a0 = g_xt + ((size_t)((2 * tm) * NK + kt) << 14);
                const unsigned char* a1 = g_xt + ((size_t)((2 * tm + 1) * NK + kt) << 14);
                const unsigned char* b0 = g_wt + ((size_t)(tn * NK + kt) << 14);
                uint32_t dst = sb + SM_STAGE0 + slot * STAGE_B;
                uint32_t fb = sb + slot * 16;
                MBARRIER_EXPECT_TX(fb, STAGE_B);
                bulk_g2s(dst,             a0, IMG_B, fb);
                bulk_g2s(dst + IMG_B,     a1, IMG_B, fb);
                bulk_g2s(dst + 2 * IMG_B, b0, IMG_B, fb);
            }
        }
        return;
    }

    // ---------------- compute warps ----------------
    int wm = wid & 3, wn = wid >> 2;       // 4(m) x 4(n) warps, each 64x32
    int a_r = wm * 64 + (lane & 15);                       // + mi*16
    int a_c = (lane >> 4) * 16;                            // + s*32
    int b_r = wn * 32 + ((lane >> 4) << 3) + (lane & 7);   // + nh*16
    int b_c = ((lane >> 3) & 1) * 16;                      // + s*32

    for (int t = 0; t < ntiles_mine; t++) {
        float acc[4][4][4];
#pragma unroll
        for (int i = 0; i < 4; i++)
#pragma unroll
            for (int j = 0; j < 4; j++)
#pragma unroll
                for (int c = 0; c < 4; c++) acc[i][j][c] = 0.f;

        int gbase = t * NK;
        for (int kt = 0; kt < NK; kt++) {
            int g = gbase + kt, slot = g & 3;
            MBARRIER_WAIT_PARITY(sb + slot * 16, (g >> 2) & 1);

            uint32_t sa = sb + SM_STAGE0 + slot * STAGE_B;  // A: 256 rows x 128B (2 images)
            uint32_t sbB = sa + 2 * IMG_B;                   // B: 128 rows x 128B
#pragma unroll
            for (int s = 0; s < 4; s++) {
                uint32_t af[4][4];
#pragma unroll
                for (int mi = 0; mi < 4; mi++)
                    ldsm_x4(af[mi][0], af[mi][1], af[mi][2], af[mi][3],
                            sa + sw128((a_r + mi * 16) * 128 + s * 32 + a_c));
                uint32_t bf[4][2];
#pragma unroll
                for (int nh = 0; nh < 2; nh++) {
                    uint32_t r0, r1, r2, r3;
                    ldsm_x4(r0, r1, r2, r3,
                            sbB + sw128((b_r + nh * 16) * 128 + s * 32 + b_c));
                    bf[nh * 2][0] = r0; bf[nh * 2][1] = r1;
                    bf[nh * 2 + 1][0] = r2; bf[nh * 2 + 1][1] = r3;
                }
#pragma unroll
                for (int mi = 0; mi < 4; mi++)
#pragma unroll
                    for (int ni = 0; ni < 4; ni++)
                        mma16816(acc[mi][ni], af[mi], bf[ni][0], bf[ni][1]);
            }
            if (lane == 0) MBARRIER_ARRIVE(sb + slot * 16 + 8);   // stage consumed
        }

        // epilogue — no barrier; producer already filling next tile's stages
        int cl = bid + t * NSM;
        size_t m0 = (size_t)(cl & 31) * BM, n0 = (size_t)(cl >> 5) * BN;
        size_t mw = m0 + wm * 64 + (lane >> 2);
        size_t nw = n0 + wn * 32 + (lane & 3) * 2;
        float bv0[4], bv1[4];
#pragma unroll
        for (int ni = 0; ni < 4; ni++) {
            bv0[ni] = __ldg(bias + nw + ni * 8);
            bv1[ni] = __ldg(bias + nw + ni * 8 + 1);
        }
#pragma unroll
        for (int mi = 0; mi < 4; mi++) {
#pragma unroll
            for (int ni = 0; ni < 4; ni++) {
                size_t n = nw + ni * 8;
                float* p0 = out + (mw + mi * 16) * N_TOT + n;
                float* p1 = out + (mw + mi * 16 + 8) * N_TOT + n;
                st_cs_v2(p0, acc[mi][ni][0] + bv0[ni], acc[mi][ni][1] + bv1[ni]);
                st_cs_v2(p1, acc[mi][ni][2] + bv0[ni], acc[mi][ni][3] + bv1[ni]);
            }
        }
    }
}

// ---------------- launch ----------------
extern "C" void kernel_launch(void* const* d_in, const int* in_sizes, int n_in,
                              void* d_out, int out_size) {
    const float* x    = (const float*)d_in[0];
    const int*   w    = (const int*)d_in[1];
    const float* sz   = (const float*)d_in[2];
    const float* bias = (const float*)d_in[3];
    float* out = (float*)d_out;

    cudaFuncSetAttribute(gemm_kernel, cudaFuncAttributeMaxDynamicSharedMemorySize, SMEM_TOTAL);

    convert_x_kernel<<<(M_TOT * K_TOT / 8) / 256, 256>>>(x);
    dequant_kernel<<<(N_TOT * K_TOT / 8) / 256, 256>>>(w, sz);
    gemm_kernel<<<NSM, 544, SMEM_TOTAL>>>(bias, out);
}